// round 12
// baseline (speedup 1.0000x reference)
#include <cuda_runtime.h>
#include <cuda_fp16.h>
#include <math.h>
#include <stdint.h>

#define BQ 128
#define NQ 512
#define HQ 128
#define M2 65536

// ---------------- scratch (allocation-free rule) ----------------
__device__ float    g_a [(size_t)M2 * HQ];
__device__ float    g_z [(size_t)M2 * HQ];
__device__ float    g_rh[(size_t)M2 * HQ];
__device__ float    g_h0[(size_t)M2 * HQ];
__device__ float    g_h1[(size_t)M2 * HQ];
__device__ uint32_t g_Wh[12 * (size_t)HQ * HQ / 2];  // packed half2 k-pairs:
// [0,1]=wz(hi,lo) [2,3]=uz [4,5]=wr [6,7]=ur [8,9]=w [10,11]=u ; each 8192 words

// ---------------- helpers ----------------
__device__ __forceinline__ void cpa16(uint32_t dst, const void* src) {
    asm volatile("cp.async.cg.shared.global [%0], [%1], 16;" :: "r"(dst), "l"(src));
}
#define CP_COMMIT() asm volatile("cp.async.commit_group;" ::: "memory")
#define CP_WAIT1()  asm volatile("cp.async.wait_group 1;" ::: "memory")
#define CP_WAIT0()  asm volatile("cp.async.wait_group 0;" ::: "memory")

__device__ __forceinline__ uint32_t smem_u32(const void* p) {
    uint32_t a;
    asm("{ .reg .u64 t; cvta.to.shared.u64 t, %1; cvt.u32.u64 %0, t; }" : "=r"(a) : "l"(p));
    return a;
}
// Split (x,y) into packed fp16 hi pair + fp16 residual pair (Markidis split).
__device__ __forceinline__ void hsplit2(float x, float y, uint32_t& hi, uint32_t& lo) {
    __half hx = __float2half_rn(x);
    __half hy = __float2half_rn(y);
    __half lx = __float2half_rn(x - __half2float(hx));
    __half ly = __float2half_rn(y - __half2float(hy));
    __half2 H = __halves2half2(hx, hy);
    __half2 L = __halves2half2(lx, ly);
    hi = *reinterpret_cast<uint32_t*>(&H);
    lo = *reinterpret_cast<uint32_t*>(&L);
}
__device__ __forceinline__ void mma16(float* c, const uint32_t* a, const uint32_t* b) {
    asm volatile(
        "mma.sync.aligned.m16n8k16.row.col.f32.f16.f16.f32 "
        "{%0,%1,%2,%3}, {%4,%5,%6,%7}, {%8,%9}, {%0,%1,%2,%3};"
        : "+f"(c[0]), "+f"(c[1]), "+f"(c[2]), "+f"(c[3])
        : "r"(a[0]), "r"(a[1]), "r"(a[2]), "r"(a[3]), "r"(b[0]), "r"(b[1]));
}

// ---------------------------------------------------------------------------
// Weight split pre-pass: fp32 [j][128] -> packed half2 k-pairs [j][64] hi + lo
// ---------------------------------------------------------------------------
__global__ __launch_bounds__(256)
void k_splith(const float* __restrict__ s, uint32_t* __restrict__ hi,
              uint32_t* __restrict__ lo, int n4)
{
    int i = blockIdx.x * blockDim.x + threadIdx.x;
    if (i >= n4) return;
    float4 v = reinterpret_cast<const float4*>(s)[i];
    uint32_t h0, l0, h1, l1;
    hsplit2(v.x, v.y, h0, l0);
    hsplit2(v.z, v.w, h1, l1);
    uint2 H; H.x = h0; H.y = h1;
    uint2 L; L.x = l0; L.y = l1;
    reinterpret_cast<uint2*>(hi)[i] = H;
    reinterpret_cast<uint2*>(lo)[i] = L;
}

// ---------------------------------------------------------------------------
// a-GEMM: a[b,n,h] = sum_m A[b,m,n]*h[b,m,h] + bias[h]  (raw fp32 in/out)
// K-major smem [kpair][i], stride 136 words, K-chunk 16 (8 pairs), C=32.
// Tiles: Ahi, Alo, Hhi, Hlo (8x136 words each). 2-stage. smem 34816 B.
// ---------------------------------------------------------------------------
#define AT_W 1088            // words per tile (8*136)
#define AS_W 4352            // words per stage (4 tiles)
__global__ __launch_bounds__(256, 2)
void k_mma_a(const float* __restrict__ A, const float* __restrict__ Hp,
             const float* __restrict__ bias, float* __restrict__ outp)
{
    extern __shared__ uint32_t su[];
    const int t = threadIdx.x, lane = t & 31, wid = t >> 5;
    const int wi = wid & 1, wj = wid >> 1;
    const int g = lane >> 2, tq = lane & 3;
    const int b = blockIdx.y, n0 = blockIdx.x * 128;

    const float* Ab = A  + (size_t)b * NQ * NQ + n0;
    const float* Hb = Hp + (size_t)b * NQ * HQ;

    float acc[4][4][4];
#pragma unroll
    for (int a_ = 0; a_ < 4; a_++)
#pragma unroll
        for (int b_ = 0; b_ < 4; b_++)
#pragma unroll
            for (int c_ = 0; c_ < 4; c_++) acc[a_][b_][c_] = 0.f;

    const int C = 32;
    const int kp = t >> 5;       // 0..7 (k-pair within chunk)
    const int c4 = t & 31;       // float4 col index 0..31
    float4 rA0, rA1, rH0, rH1;

#define A_LDG(cc)                                                              \
    {                                                                          \
        const int m0 = (cc) * 16 + kp * 2;                                     \
        rA0 = *reinterpret_cast<const float4*>(Ab + (size_t)m0 * NQ + c4 * 4); \
        rA1 = *reinterpret_cast<const float4*>(Ab + (size_t)(m0+1)*NQ + c4*4); \
        rH0 = *reinterpret_cast<const float4*>(Hb + (size_t)m0 * HQ + c4 * 4); \
        rH1 = *reinterpret_cast<const float4*>(Hb + (size_t)(m0+1)*HQ + c4*4); \
    }
#define A_STS(st)                                                              \
    {                                                                          \
        uint32_t* s0 = su + (st) * AS_W;                                       \
        const int off = kp * 136 + c4 * 4;                                     \
        uint4 H, L;                                                            \
        hsplit2(rA0.x, rA1.x, H.x, L.x); hsplit2(rA0.y, rA1.y, H.y, L.y);      \
        hsplit2(rA0.z, rA1.z, H.z, L.z); hsplit2(rA0.w, rA1.w, H.w, L.w);      \
        *reinterpret_cast<uint4*>(s0 + off) = H;                               \
        *reinterpret_cast<uint4*>(s0 + AT_W + off) = L;                        \
        hsplit2(rH0.x, rH1.x, H.x, L.x); hsplit2(rH0.y, rH1.y, H.y, L.y);      \
        hsplit2(rH0.z, rH1.z, H.z, L.z); hsplit2(rH0.w, rH1.w, H.w, L.w);      \
        *reinterpret_cast<uint4*>(s0 + 2 * AT_W + off) = H;                    \
        *reinterpret_cast<uint4*>(s0 + 3 * AT_W + off) = L;                    \
    }

    A_LDG(0);
    for (int c = 0; c < C; c++) {
        const int sc = c & 1;
        A_STS(sc);
        if (c + 1 < C) A_LDG(c + 1);
        __syncthreads();
        const uint32_t* Xh = su + sc * AS_W;
        const uint32_t* Xl = Xh + AT_W;
        const uint32_t* Wh = Xh + 2 * AT_W;
        const uint32_t* Wl = Xh + 3 * AT_W;
        uint32_t ah[4][4], al[4][4], bh[4][2], bl[4][2];
#pragma unroll
        for (int mf = 0; mf < 4; mf++) {
            const int r = wi * 64 + mf * 16 + g;
            ah[mf][0] = Xh[tq * 136 + r];
            ah[mf][1] = Xh[tq * 136 + r + 8];
            ah[mf][2] = Xh[(tq + 4) * 136 + r];
            ah[mf][3] = Xh[(tq + 4) * 136 + r + 8];
            al[mf][0] = Xl[tq * 136 + r];
            al[mf][1] = Xl[tq * 136 + r + 8];
            al[mf][2] = Xl[(tq + 4) * 136 + r];
            al[mf][3] = Xl[(tq + 4) * 136 + r + 8];
        }
#pragma unroll
        for (int nf = 0; nf < 4; nf++) {
            const int cj = wj * 32 + nf * 8 + g;
            bh[nf][0] = Wh[tq * 136 + cj];
            bh[nf][1] = Wh[(tq + 4) * 136 + cj];
            bl[nf][0] = Wl[tq * 136 + cj];
            bl[nf][1] = Wl[(tq + 4) * 136 + cj];
        }
#pragma unroll
        for (int nf = 0; nf < 4; nf++)
#pragma unroll
            for (int mf = 0; mf < 4; mf++) mma16(acc[mf][nf], ah[mf], bh[nf]);
#pragma unroll
        for (int nf = 0; nf < 4; nf++)
#pragma unroll
            for (int mf = 0; mf < 4; mf++) mma16(acc[mf][nf], al[mf], bh[nf]);
#pragma unroll
        for (int nf = 0; nf < 4; nf++)
#pragma unroll
            for (int mf = 0; mf < 4; mf++) mma16(acc[mf][nf], ah[mf], bl[nf]);
        __syncthreads();
    }
#undef A_LDG
#undef A_STS

    const size_t obase = (size_t)b * NQ * HQ;
#pragma unroll
    for (int mf = 0; mf < 4; mf++) {
#pragma unroll
        for (int h2 = 0; h2 < 2; h2++) {
            const int i = n0 + wi * 64 + mf * 16 + g + h2 * 8;
            const size_t rb = obase + (size_t)i * HQ;
#pragma unroll
            for (int nf = 0; nf < 4; nf++) {
                const int j = wj * 32 + nf * 8 + 2 * tq;
                const float2 bb = *reinterpret_cast<const float2*>(bias + j);
                float2 v;
                v.x = acc[mf][nf][h2 * 2 + 0] + bb.x;
                v.y = acc[mf][nf][h2 * 2 + 1] + bb.y;
                *reinterpret_cast<float2*>(outp + rb + j) = v;
            }
        }
    }
}

// ---------------------------------------------------------------------------
// Fused z+r: [z|r] = a@[wz|wr]^T + h@[uz|ur]^T (+biases)
// CTA 64 rows x 256 cols, warp tile 64x32. M-major smem [i][kpair], stride 12.
// Tiles: Xh/Xl 64x12, Wh/Wl 256x12. 2-stage. smem 61440 B.
// ---------------------------------------------------------------------------
#define ZT_X 768             // 64*12
#define ZT_W 3072            // 256*12
#define ZS_W 7680
__global__ __launch_bounds__(256, 2)
void k_zr(const float* __restrict__ ap, const float* __restrict__ hp,
          const uint32_t* __restrict__ Wsp,
          const float* __restrict__ b_wz, const float* __restrict__ b_uz,
          const float* __restrict__ b_wr, const float* __restrict__ b_ur,
          float* __restrict__ zout, float* __restrict__ rhout)
{
    extern __shared__ uint32_t su[];
    const uint32_t sb = smem_u32(su);
    const int t = threadIdx.x, lane = t & 31, wj = t >> 5;
    const int g = lane >> 2, tq = lane & 3;
    const int i0 = blockIdx.x * 64;
    const int SW = HQ * HQ / 2;   // 8192 packed words per matrix

    float acc[4][4][4];
#pragma unroll
    for (int a_ = 0; a_ < 4; a_++)
#pragma unroll
        for (int b_ = 0; b_ < 4; b_++)
#pragma unroll
            for (int c_ = 0; c_ < 4; c_++) acc[a_][b_][c_] = 0.f;

    const int C = 16;
    float4 rX;
    const int xrow = t >> 2, xf4 = t & 3;

#define Z_LDGX(cc)                                                             \
    {                                                                          \
        const int half = (cc) >> 3;                                            \
        const int kc = ((cc) & 7) * 16;                                        \
        const float* xp = (half ? hp : ap) + (size_t)i0 * HQ + kc;             \
        rX = *reinterpret_cast<const float4*>(xp + (size_t)xrow*HQ + xf4*4);   \
    }
#define Z_STSX(st)                                                             \
    {                                                                          \
        uint32_t* s0 = su + (st) * ZS_W;                                       \
        const int off = xrow * 12 + xf4 * 2;                                   \
        uint2 H, L;                                                            \
        hsplit2(rX.x, rX.y, H.x, L.x);                                         \
        hsplit2(rX.z, rX.w, H.y, L.y);                                         \
        *reinterpret_cast<uint2*>(s0 + off) = H;                               \
        *reinterpret_cast<uint2*>(s0 + ZT_X + off) = L;                        \
    }
#define Z_CPAW(cc, st)                                                         \
    {                                                                          \
        const int half = (cc) >> 3;                                            \
        const int kw = ((cc) & 7) * 8;                                         \
        const uint32_t* w1h = Wsp + (half ? 2 : 0) * SW + kw;                  \
        const uint32_t* w1l = Wsp + (half ? 3 : 1) * SW + kw;                  \
        const uint32_t* w2h = Wsp + (half ? 6 : 4) * SW + kw;                  \
        const uint32_t* w2l = Wsp + (half ? 7 : 5) * SW + kw;                  \
        const uint32_t s0 = sb + (uint32_t)(st) * ZS_W * 4;                    \
        _Pragma("unroll")                                                      \
        for (int p = 0; p < 2; p++) {                                          \
            const int idx = t + p * 256;                                       \
            const int row = idx >> 1, f4 = idx & 1;                            \
            const uint32_t off = (uint32_t)(row * 12 + f4 * 4) * 4;            \
            const uint32_t* sh = (row < 128) ? (w1h + (size_t)row * 64)        \
                                             : (w2h + (size_t)(row-128)*64);  \
            const uint32_t* sl = (row < 128) ? (w1l + (size_t)row * 64)        \
                                             : (w2l + (size_t)(row-128)*64);  \
            cpa16(s0 + 2 * ZT_X * 4 + off,          sh + f4 * 4);              \
            cpa16(s0 + (2 * ZT_X + ZT_W) * 4 + off, sl + f4 * 4);              \
        }                                                                      \
        CP_COMMIT();                                                           \
    }

    Z_LDGX(0);
    Z_CPAW(0, 0);
    for (int c = 0; c < C; c++) {
        const int sc = c & 1;
        Z_STSX(sc);
        if (c + 1 < C) { Z_LDGX(c + 1); Z_CPAW(c + 1, (c + 1) & 1); CP_WAIT1(); }
        else           { CP_WAIT0(); }
        __syncthreads();
        const uint32_t* Xh = su + sc * ZS_W;
        const uint32_t* Xl = Xh + ZT_X;
        const uint32_t* Wh = Xh + 2 * ZT_X;
        const uint32_t* Wl = Wh + ZT_W;
        uint32_t ah[4][4], al[4][4], bh[4][2], bl[4][2];
#pragma unroll
        for (int mf = 0; mf < 4; mf++) {
            const int r = mf * 16 + g;
            ah[mf][0] = Xh[r * 12 + tq];
            ah[mf][1] = Xh[(r + 8) * 12 + tq];
            ah[mf][2] = Xh[r * 12 + tq + 4];
            ah[mf][3] = Xh[(r + 8) * 12 + tq + 4];
            al[mf][0] = Xl[r * 12 + tq];
            al[mf][1] = Xl[(r + 8) * 12 + tq];
            al[mf][2] = Xl[r * 12 + tq + 4];
            al[mf][3] = Xl[(r + 8) * 12 + tq + 4];
        }
#pragma unroll
        for (int nf = 0; nf < 4; nf++) {
            const int cj = wj * 32 + nf * 8 + g;
            bh[nf][0] = Wh[cj * 12 + tq];
            bh[nf][1] = Wh[cj * 12 + tq + 4];
            bl[nf][0] = Wl[cj * 12 + tq];
            bl[nf][1] = Wl[cj * 12 + tq + 4];
        }
#pragma unroll
        for (int nf = 0; nf < 4; nf++)
#pragma unroll
            for (int mf = 0; mf < 4; mf++) mma16(acc[mf][nf], ah[mf], bh[nf]);
#pragma unroll
        for (int nf = 0; nf < 4; nf++)
#pragma unroll
            for (int mf = 0; mf < 4; mf++) mma16(acc[mf][nf], al[mf], bh[nf]);
#pragma unroll
        for (int nf = 0; nf < 4; nf++)
#pragma unroll
            for (int mf = 0; mf < 4; mf++) mma16(acc[mf][nf], ah[mf], bl[nf]);
        __syncthreads();
    }
#undef Z_LDGX
#undef Z_STSX
#undef Z_CPAW

#pragma unroll
    for (int mf = 0; mf < 4; mf++) {
#pragma unroll
        for (int h2 = 0; h2 < 2; h2++) {
            const int i = i0 + mf * 16 + g + h2 * 8;
            const size_t rb = (size_t)i * HQ;
#pragma unroll
            for (int nf = 0; nf < 4; nf++) {
                const int j = wj * 32 + nf * 8 + 2 * tq;
                if (wj < 4) {
                    const float2 bb1 = *reinterpret_cast<const float2*>(b_wz + j);
                    const float2 bb2 = *reinterpret_cast<const float2*>(b_uz + j);
                    float v0 = acc[mf][nf][h2 * 2 + 0] + bb1.x + bb2.x;
                    float v1 = acc[mf][nf][h2 * 2 + 1] + bb1.y + bb2.y;
                    float2 o;
                    o.x = 1.f / (1.f + __expf(-v0));
                    o.y = 1.f / (1.f + __expf(-v1));
                    *reinterpret_cast<float2*>(zout + rb + j) = o;
                } else {
                    const int jj = j - 128;
                    const float2 bb1 = *reinterpret_cast<const float2*>(b_wr + jj);
                    const float2 bb2 = *reinterpret_cast<const float2*>(b_ur + jj);
                    float v0 = acc[mf][nf][h2 * 2 + 0] + bb1.x + bb2.x;
                    float v1 = acc[mf][nf][h2 * 2 + 1] + bb1.y + bb2.y;
                    const float2 hv = *reinterpret_cast<const float2*>(hp + rb + jj);
                    float2 o;
                    o.x = hv.x * (1.f / (1.f + __expf(-v0)));
                    o.y = hv.y * (1.f / (1.f + __expf(-v1)));
                    *reinterpret_cast<float2*>(rhout + rb + jj) = o;
                }
            }
        }
    }
}

// ---------------------------------------------------------------------------
// c-gate: D = a@w^T + rh@u^T (+b); h' = (1-z)h + z tanh(D)
// CTA 128x128, M-major smem [i][kpair] stride 12, K-chunk 16, C=16, 2-stage.
// Tiles: Xh/Xl/Wh/Wl 128x12 = 1536 w each; stage 6144 w; smem 49152 B.
// ---------------------------------------------------------------------------
#define GT_W 1536
#define GS_W 6144
__global__ __launch_bounds__(256, 2)
void k_cgate(const float* __restrict__ ap, const float* __restrict__ rhp,
             const uint32_t* __restrict__ Wsp,
             const float* __restrict__ b1, const float* __restrict__ b2,
             const float* __restrict__ hp, const float* __restrict__ zp,
             float* __restrict__ outp)
{
    extern __shared__ uint32_t su[];
    const uint32_t sb = smem_u32(su);
    const int t = threadIdx.x, lane = t & 31, wid = t >> 5;
    const int wi = wid & 1, wj = wid >> 1;
    const int g = lane >> 2, tq = lane & 3;
    const int i0 = blockIdx.x * 128;
    const int SW = HQ * HQ / 2;

    float acc[4][4][4];
#pragma unroll
    for (int a_ = 0; a_ < 4; a_++)
#pragma unroll
        for (int b_ = 0; b_ < 4; b_++)
#pragma unroll
            for (int c_ = 0; c_ < 4; c_++) acc[a_][b_][c_] = 0.f;

    const int C = 16;
    float4 rX[2];

#define G_LDGX(cc)                                                             \
    {                                                                          \
        const int gg = (cc) >> 3;                                              \
        const int kc = ((cc) & 7) * 16;                                        \
        const float* xp = (gg ? rhp : ap) + (size_t)i0 * HQ + kc;              \
        _Pragma("unroll")                                                      \
        for (int p = 0; p < 2; p++) {                                          \
            const int idx = t + p * 256;                                       \
            const int row = idx >> 2, f4 = idx & 3;                            \
            rX[p] = *reinterpret_cast<const float4*>(                          \
                xp + (size_t)row * HQ + f4 * 4);                               \
        }                                                                      \
    }
#define G_STSX(st)                                                             \
    {                                                                          \
        uint32_t* s0 = su + (st) * GS_W;                                       \
        _Pragma("unroll")                                                      \
        for (int p = 0; p < 2; p++) {                                          \
            const int idx = t + p * 256;                                       \
            const int row = idx >> 2, f4 = idx & 3;                            \
            const int off = row * 12 + f4 * 2;                                 \
            uint2 H, L;                                                        \
            hsplit2(rX[p].x, rX[p].y, H.x, L.x);                               \
            hsplit2(rX[p].z, rX[p].w, H.y, L.y);                               \
            *reinterpret_cast<uint2*>(s0 + off) = H;                           \
            *reinterpret_cast<uint2*>(s0 + GT_W + off) = L;                    \
        }                                                                      \
    }
#define G_CPAW(cc, st)                                                         \
    {                                                                          \
        const int gg = (cc) >> 3;                                              \
        const int kw = ((cc) & 7) * 8;                                         \
        const uint32_t* wh_ = Wsp + (gg ? 10 : 8) * SW + kw;                   \
        const uint32_t* wl_ = Wsp + (gg ? 11 : 9) * SW + kw;                   \
        const uint32_t s0 = sb + (uint32_t)(st) * GS_W * 4;                    \
        {                                                                      \
            const int row = t >> 1, f4 = t & 1;                                \
            const uint32_t off = (uint32_t)(row * 12 + f4 * 4) * 4;            \
            cpa16(s0 + 2 * GT_W * 4 + off, wh_ + (size_t)row * 64 + f4 * 4);   \
            cpa16(s0 + 3 * GT_W * 4 + off, wl_ + (size_t)row * 64 + f4 * 4);   \
        }                                                                      \
        CP_COMMIT();                                                           \
    }

    G_LDGX(0);
    G_CPAW(0, 0);
    for (int c = 0; c < C; c++) {
        const int sc = c & 1;
        G_STSX(sc);
        if (c + 1 < C) { G_LDGX(c + 1); G_CPAW(c + 1, (c + 1) & 1); CP_WAIT1(); }
        else           { CP_WAIT0(); }
        __syncthreads();
        const uint32_t* Xh = su + sc * GS_W;
        const uint32_t* Xl = Xh + GT_W;
        const uint32_t* Wh = Xh + 2 * GT_W;
        const uint32_t* Wl = Xh + 3 * GT_W;
        uint32_t ah[4][4], al[4][4], bh[4][2], bl[4][2];
#pragma unroll
        for (int mf = 0; mf < 4; mf++) {
            const int r = wi * 64 + mf * 16 + g;
            ah[mf][0] = Xh[r * 12 + tq];
            ah[mf][1] = Xh[(r + 8) * 12 + tq];
            ah[mf][2] = Xh[r * 12 + tq + 4];
            ah[mf][3] = Xh[(r + 8) * 12 + tq + 4];
            al[mf][0] = Xl[r * 12 + tq];
            al[mf][1] = Xl[(r + 8) * 12 + tq];
            al[mf][2] = Xl[r * 12 + tq + 4];
            al[mf][3] = Xl[(r + 8) * 12 + tq + 4];
        }
#pragma unroll
        for (int nf = 0; nf < 4; nf++) {
            const int cj = wj * 32 + nf * 8 + g;
            bh[nf][0] = Wh[cj * 12 + tq];
            bh[nf][1] = Wh[cj * 12 + tq + 4];
            bl[nf][0] = Wl[cj * 12 + tq];
            bl[nf][1] = Wl[cj * 12 + tq + 4];
        }
#pragma unroll
        for (int nf = 0; nf < 4; nf++)
#pragma unroll
            for (int mf = 0; mf < 4; mf++) mma16(acc[mf][nf], ah[mf], bh[nf]);
#pragma unroll
        for (int nf = 0; nf < 4; nf++)
#pragma unroll
            for (int mf = 0; mf < 4; mf++) mma16(acc[mf][nf], al[mf], bh[nf]);
#pragma unroll
        for (int nf = 0; nf < 4; nf++)
#pragma unroll
            for (int mf = 0; mf < 4; mf++) mma16(acc[mf][nf], ah[mf], bl[nf]);
        __syncthreads();
    }
#undef G_LDGX
#undef G_STSX
#undef G_CPAW

#pragma unroll
    for (int mf = 0; mf < 4; mf++) {
#pragma unroll
        for (int h2 = 0; h2 < 2; h2++) {
            const int i = i0 + wi * 64 + mf * 16 + g + h2 * 8;
            const size_t rb = (size_t)i * HQ;
#pragma unroll
            for (int nf = 0; nf < 4; nf++) {
                const int j = wj * 32 + nf * 8 + 2 * tq;
                const float2 bb1 = *reinterpret_cast<const float2*>(b1 + j);
                const float2 bb2 = *reinterpret_cast<const float2*>(b2 + j);
                float v0 = acc[mf][nf][h2 * 2 + 0] + bb1.x + bb2.x;
                float v1 = acc[mf][nf][h2 * 2 + 1] + bb1.y + bb2.y;
                const float2 hv = *reinterpret_cast<const float2*>(hp + rb + j);
                const float2 zz = *reinterpret_cast<const float2*>(zp + rb + j);
                float2 o;
                o.x = (1.f - zz.x) * hv.x + zz.x * tanhf(v0);
                o.y = (1.f - zz.y) * hv.y + zz.y * tanhf(v1);
                *reinterpret_cast<float2*>(outp + rb + j) = o;
            }
        }
    }
}

// ---------------------------------------------------------------------------
// Host launcher
// ---------------------------------------------------------------------------
extern "C" void kernel_launch(void* const* d_in, const int* in_sizes, int n_in,
                              void* d_out, int out_size)
{
    const float* A      = (const float*)d_in[0];
    const float* hidden = (const float*)d_in[1];
    const float* b_ah   = (const float*)d_in[2];
    const float* w_z    = (const float*)d_in[3];
    const float* b_wz   = (const float*)d_in[4];
    const float* u_z    = (const float*)d_in[5];
    const float* b_uz   = (const float*)d_in[6];
    const float* w_r    = (const float*)d_in[7];
    const float* b_wr   = (const float*)d_in[8];
    const float* u_r    = (const float*)d_in[9];
    const float* b_ur   = (const float*)d_in[10];
    const float* w      = (const float*)d_in[11];
    const float* b_w    = (const float*)d_in[12];
    const float* u      = (const float*)d_in[13];
    const float* b_u    = (const float*)d_in[14];
    float* out = (float*)d_out;

    float *ga, *gz, *grh, *h0, *h1;
    uint32_t* Wsp;
    cudaGetSymbolAddress((void**)&ga,  g_a);
    cudaGetSymbolAddress((void**)&gz,  g_z);
    cudaGetSymbolAddress((void**)&grh, g_rh);
    cudaGetSymbolAddress((void**)&h0,  g_h0);
    cudaGetSymbolAddress((void**)&h1,  g_h1);
    cudaGetSymbolAddress((void**)&Wsp, g_Wh);

    cudaFuncSetAttribute(k_mma_a, cudaFuncAttributeMaxDynamicSharedMemorySize, 34816);
    cudaFuncSetAttribute(k_zr,    cudaFuncAttributeMaxDynamicSharedMemorySize, 61440);
    cudaFuncSetAttribute(k_cgate, cudaFuncAttributeMaxDynamicSharedMemorySize, 49152);

    const int S  = HQ * HQ;      // 16384 floats per matrix
    const int SW = S / 2;        // 8192 packed words per matrix
    k_splith<<<S / 1024, 256>>>(w_z, Wsp + 0 * SW,  Wsp + 1 * SW,  S / 4);
    k_splith<<<S / 1024, 256>>>(u_z, Wsp + 2 * SW,  Wsp + 3 * SW,  S / 4);
    k_splith<<<S / 1024, 256>>>(w_r, Wsp + 4 * SW,  Wsp + 5 * SW,  S / 4);
    k_splith<<<S / 1024, 256>>>(u_r, Wsp + 6 * SW,  Wsp + 7 * SW,  S / 4);
    k_splith<<<S / 1024, 256>>>(w,   Wsp + 8 * SW,  Wsp + 9 * SW,  S / 4);
    k_splith<<<S / 1024, 256>>>(u,   Wsp + 10 * SW, Wsp + 11 * SW, S / 4);

    const float* hpr[4] = { hidden, h0, h1, h0 };
    float*       hnr[4] = { h0, h1, h0, out };

    for (int s = 0; s < 4; s++) {
        const float* hp = hpr[s];
        k_mma_a<<<dim3(4, BQ), 256, 34816>>>(A, hp, b_ah, ga);
        k_zr<<<M2 / 64, 256, 61440>>>(ga, hp, Wsp, b_wz, b_uz, b_wr, b_ur, gz, grh);
        k_cgate<<<M2 / 128, 256, 49152>>>(ga, grh, Wsp, b_w, b_u, hp, gz, hnr[s]);
    }
}

// round 14
// speedup vs baseline: 1.0405x; 1.0405x over previous
#include <cuda_runtime.h>
#include <cuda_fp16.h>
#include <math.h>
#include <stdint.h>

#define BQ 128
#define NQ 512
#define HQ 128
#define M2 65536

// ---------------- scratch (allocation-free rule) ----------------
__device__ float    g_a [(size_t)M2 * HQ];
__device__ float    g_z [(size_t)M2 * HQ];
__device__ float    g_rh[(size_t)M2 * HQ];
__device__ float    g_h0[(size_t)M2 * HQ];
__device__ float    g_h1[(size_t)M2 * HQ];
__device__ uint32_t g_Wh[12 * (size_t)HQ * HQ / 2];  // packed half2 k-pairs:
// [0,1]=wz(hi,lo) [2,3]=uz [4,5]=wr [6,7]=ur [8,9]=w [10,11]=u ; each 8192 words

// ---------------- helpers ----------------
__device__ __forceinline__ void cpa16(uint32_t dst, const void* src) {
    asm volatile("cp.async.cg.shared.global [%0], [%1], 16;" :: "r"(dst), "l"(src));
}
#define CP_COMMIT() asm volatile("cp.async.commit_group;" ::: "memory")
#define CP_WAIT1()  asm volatile("cp.async.wait_group 1;" ::: "memory")
#define CP_WAIT0()  asm volatile("cp.async.wait_group 0;" ::: "memory")

__device__ __forceinline__ uint32_t smem_u32(const void* p) {
    uint32_t a;
    asm("{ .reg .u64 t; cvta.to.shared.u64 t, %1; cvt.u32.u64 %0, t; }" : "=r"(a) : "l"(p));
    return a;
}
// Split (x,y) into packed fp16 hi pair + fp16 residual pair (Markidis split).
__device__ __forceinline__ void hsplit2(float x, float y, uint32_t& hi, uint32_t& lo) {
    __half hx = __float2half_rn(x);
    __half hy = __float2half_rn(y);
    __half lx = __float2half_rn(x - __half2float(hx));
    __half ly = __float2half_rn(y - __half2float(hy));
    __half2 H = __halves2half2(hx, hy);
    __half2 L = __halves2half2(lx, ly);
    hi = *reinterpret_cast<uint32_t*>(&H);
    lo = *reinterpret_cast<uint32_t*>(&L);
}
__device__ __forceinline__ void mma16(float* c, const uint32_t* a, const uint32_t* b) {
    asm volatile(
        "mma.sync.aligned.m16n8k16.row.col.f32.f16.f16.f32 "
        "{%0,%1,%2,%3}, {%4,%5,%6,%7}, {%8,%9}, {%0,%1,%2,%3};"
        : "+f"(c[0]), "+f"(c[1]), "+f"(c[2]), "+f"(c[3])
        : "r"(a[0]), "r"(a[1]), "r"(a[2]), "r"(a[3]), "r"(b[0]), "r"(b[1]));
}

// ---------------------------------------------------------------------------
// Weight split pre-pass (fused: all 6 matrices in one launch via blockIdx.y)
// ---------------------------------------------------------------------------
__global__ __launch_bounds__(256)
void k_splith6(const float* __restrict__ s0, const float* __restrict__ s1,
               const float* __restrict__ s2, const float* __restrict__ s3,
               const float* __restrict__ s4, const float* __restrict__ s5,
               uint32_t* __restrict__ Wsp)
{
    const int m = blockIdx.y;
    const float* srcs[6] = { s0, s1, s2, s3, s4, s5 };
    const float* s = srcs[m];
    const int SW = HQ * HQ / 2;
    uint32_t* hi = Wsp + (size_t)(2 * m) * SW;
    uint32_t* lo = Wsp + (size_t)(2 * m + 1) * SW;
    int i = blockIdx.x * blockDim.x + threadIdx.x;    // float4 index, 4096 total
    float4 v = reinterpret_cast<const float4*>(s)[i];
    uint32_t h0, l0, h1, l1;
    hsplit2(v.x, v.y, h0, l0);
    hsplit2(v.z, v.w, h1, l1);
    uint2 H; H.x = h0; H.y = h1;
    uint2 L; L.x = l0; L.y = l1;
    reinterpret_cast<uint2*>(hi)[i] = H;
    reinterpret_cast<uint2*>(lo)[i] = L;
}

// ---------------------------------------------------------------------------
// a-GEMM: a[b,n,h] = sum_m A[b,m,n]*h[b,m,h] + bias[h]  (raw fp32 in/out)
// UNCHANGED from round-9 best (1120us). K-major smem stride 136 w, K-chunk 16.
// ---------------------------------------------------------------------------
#define AT_W 1088            // words per tile (8*136)
#define AS_W 4352            // words per stage (4 tiles)
__global__ __launch_bounds__(256)
void k_mma_a(const float* __restrict__ A, const float* __restrict__ Hp,
             const float* __restrict__ bias, float* __restrict__ outp)
{
    extern __shared__ uint32_t su[];
    const int t = threadIdx.x, lane = t & 31, wid = t >> 5;
    const int wi = wid & 1, wj = wid >> 1;
    const int g = lane >> 2, tq = lane & 3;
    const int b = blockIdx.y, n0 = blockIdx.x * 128;

    const float* Ab = A  + (size_t)b * NQ * NQ + n0;
    const float* Hb = Hp + (size_t)b * NQ * HQ;

    float acc[4][4][4];
#pragma unroll
    for (int a_ = 0; a_ < 4; a_++)
#pragma unroll
        for (int b_ = 0; b_ < 4; b_++)
#pragma unroll
            for (int c_ = 0; c_ < 4; c_++) acc[a_][b_][c_] = 0.f;

    const int C = 32;
    const int kp = t >> 5;       // 0..7 (k-pair within chunk)
    const int c4 = t & 31;       // float4 col index 0..31
    float4 rA0, rA1, rH0, rH1;

#define A_LDG(cc)                                                              \
    {                                                                          \
        const int m0 = (cc) * 16 + kp * 2;                                     \
        rA0 = *reinterpret_cast<const float4*>(Ab + (size_t)m0 * NQ + c4 * 4); \
        rA1 = *reinterpret_cast<const float4*>(Ab + (size_t)(m0+1)*NQ + c4*4); \
        rH0 = *reinterpret_cast<const float4*>(Hb + (size_t)m0 * HQ + c4 * 4); \
        rH1 = *reinterpret_cast<const float4*>(Hb + (size_t)(m0+1)*HQ + c4*4); \
    }
#define A_STS(st)                                                              \
    {                                                                          \
        uint32_t* s0 = su + (st) * AS_W;                                       \
        const int off = kp * 136 + c4 * 4;                                     \
        uint4 H, L;                                                            \
        hsplit2(rA0.x, rA1.x, H.x, L.x); hsplit2(rA0.y, rA1.y, H.y, L.y);      \
        hsplit2(rA0.z, rA1.z, H.z, L.z); hsplit2(rA0.w, rA1.w, H.w, L.w);      \
        *reinterpret_cast<uint4*>(s0 + off) = H;                               \
        *reinterpret_cast<uint4*>(s0 + AT_W + off) = L;                        \
        hsplit2(rH0.x, rH1.x, H.x, L.x); hsplit2(rH0.y, rH1.y, H.y, L.y);      \
        hsplit2(rH0.z, rH1.z, H.z, L.z); hsplit2(rH0.w, rH1.w, H.w, L.w);      \
        *reinterpret_cast<uint4*>(s0 + 2 * AT_W + off) = H;                    \
        *reinterpret_cast<uint4*>(s0 + 3 * AT_W + off) = L;                    \
    }

    A_LDG(0);
    for (int c = 0; c < C; c++) {
        const int sc = c & 1;
        A_STS(sc);
        if (c + 1 < C) A_LDG(c + 1);
        __syncthreads();
        const uint32_t* Xh = su + sc * AS_W;
        const uint32_t* Xl = Xh + AT_W;
        const uint32_t* Wh = Xh + 2 * AT_W;
        const uint32_t* Wl = Xh + 3 * AT_W;
        uint32_t ah[4][4], al[4][4], bh[4][2], bl[4][2];
#pragma unroll
        for (int mf = 0; mf < 4; mf++) {
            const int r = wi * 64 + mf * 16 + g;
            ah[mf][0] = Xh[tq * 136 + r];
            ah[mf][1] = Xh[tq * 136 + r + 8];
            ah[mf][2] = Xh[(tq + 4) * 136 + r];
            ah[mf][3] = Xh[(tq + 4) * 136 + r + 8];
            al[mf][0] = Xl[tq * 136 + r];
            al[mf][1] = Xl[tq * 136 + r + 8];
            al[mf][2] = Xl[(tq + 4) * 136 + r];
            al[mf][3] = Xl[(tq + 4) * 136 + r + 8];
        }
#pragma unroll
        for (int nf = 0; nf < 4; nf++) {
            const int cj = wj * 32 + nf * 8 + g;
            bh[nf][0] = Wh[tq * 136 + cj];
            bh[nf][1] = Wh[(tq + 4) * 136 + cj];
            bl[nf][0] = Wl[tq * 136 + cj];
            bl[nf][1] = Wl[(tq + 4) * 136 + cj];
        }
#pragma unroll
        for (int nf = 0; nf < 4; nf++)
#pragma unroll
            for (int mf = 0; mf < 4; mf++) mma16(acc[mf][nf], ah[mf], bh[nf]);
#pragma unroll
        for (int nf = 0; nf < 4; nf++)
#pragma unroll
            for (int mf = 0; mf < 4; mf++) mma16(acc[mf][nf], al[mf], bh[nf]);
#pragma unroll
        for (int nf = 0; nf < 4; nf++)
#pragma unroll
            for (int mf = 0; mf < 4; mf++) mma16(acc[mf][nf], ah[mf], bl[nf]);
        __syncthreads();
    }
#undef A_LDG
#undef A_STS

    const size_t obase = (size_t)b * NQ * HQ;
#pragma unroll
    for (int mf = 0; mf < 4; mf++) {
#pragma unroll
        for (int h2 = 0; h2 < 2; h2++) {
            const int i = n0 + wi * 64 + mf * 16 + g + h2 * 8;
            const size_t rb = obase + (size_t)i * HQ;
#pragma unroll
            for (int nf = 0; nf < 4; nf++) {
                const int j = wj * 32 + nf * 8 + 2 * tq;
                const float2 bb = *reinterpret_cast<const float2*>(bias + j);
                float2 v;
                v.x = acc[mf][nf][h2 * 2 + 0] + bb.x;
                v.y = acc[mf][nf][h2 * 2 + 1] + bb.y;
                *reinterpret_cast<float2*>(outp + rb + j) = v;
            }
        }
    }
}

// ---------------------------------------------------------------------------
// Fused z+r: [z|r] = a@[wz|wr]^T + h@[uz|ur]^T (+biases)
// CTA 32 rows x 256 cols (acc 32/thread -> ~90 regs -> 2 CTA/SM naturally).
// 8 warps, warp tile 32x32 (mf=2, nf=4). M-major smem stride 12, K-chunk 16.
// stage: Xh/Xl 32x12=384 w each, Wh/Wl 256x12=3072 w each = 6912 w; x2 = 55296 B.
// ---------------------------------------------------------------------------
#define ZT_X 384             // 32*12
#define ZT_W 3072            // 256*12
#define ZS_W 6912
__global__ __launch_bounds__(256)
void k_zr(const float* __restrict__ ap, const float* __restrict__ hp,
          const uint32_t* __restrict__ Wsp,
          const float* __restrict__ b_wz, const float* __restrict__ b_uz,
          const float* __restrict__ b_wr, const float* __restrict__ b_ur,
          float* __restrict__ zout, float* __restrict__ rhout)
{
    extern __shared__ uint32_t su[];
    const uint32_t sb = smem_u32(su);
    const int t = threadIdx.x, lane = t & 31, wj = t >> 5;
    const int g = lane >> 2, tq = lane & 3;
    const int i0 = blockIdx.x * 32;
    const int SW = HQ * HQ / 2;   // 8192 packed words per matrix

    float acc[2][4][4];
#pragma unroll
    for (int a_ = 0; a_ < 2; a_++)
#pragma unroll
        for (int b_ = 0; b_ < 4; b_++)
#pragma unroll
            for (int c_ = 0; c_ < 4; c_++) acc[a_][b_][c_] = 0.f;

    const int C = 16;
    float4 rX;
    const int xrow = t >> 2, xf4 = t & 3;   // threads 0..127 load X (32 rows x 4 f4)

#define Z_LDGX(cc)                                                             \
    if (t < 128) {                                                             \
        const int half = (cc) >> 3;                                            \
        const int kc = ((cc) & 7) * 16;                                        \
        const float* xp = (half ? hp : ap) + (size_t)i0 * HQ + kc;             \
        rX = *reinterpret_cast<const float4*>(xp + (size_t)xrow*HQ + xf4*4);   \
    }
#define Z_STSX(st)                                                             \
    if (t < 128) {                                                             \
        uint32_t* s0 = su + (st) * ZS_W;                                       \
        const int off = xrow * 12 + xf4 * 2;                                   \
        uint2 H, L;                                                            \
        hsplit2(rX.x, rX.y, H.x, L.x);                                         \
        hsplit2(rX.z, rX.w, H.y, L.y);                                         \
        *reinterpret_cast<uint2*>(s0 + off) = H;                               \
        *reinterpret_cast<uint2*>(s0 + ZT_X + off) = L;                        \
    }
#define Z_CPAW(cc, st)                                                         \
    {                                                                          \
        const int half = (cc) >> 3;                                            \
        const int kw = ((cc) & 7) * 8;                                         \
        const uint32_t* w1h = Wsp + (half ? 2 : 0) * SW + kw;                  \
        const uint32_t* w1l = Wsp + (half ? 3 : 1) * SW + kw;                  \
        const uint32_t* w2h = Wsp + (half ? 6 : 4) * SW + kw;                  \
        const uint32_t* w2l = Wsp + (half ? 7 : 5) * SW + kw;                  \
        const uint32_t s0 = sb + (uint32_t)(st) * ZS_W * 4;                    \
        _Pragma("unroll")                                                      \
        for (int p = 0; p < 2; p++) {                                          \
            const int idx = t + p * 256;                                       \
            const int row = idx >> 1, f4 = idx & 1;                            \
            const uint32_t off = (uint32_t)(row * 12 + f4 * 4) * 4;            \
            const uint32_t* sh = (row < 128) ? (w1h + (size_t)row * 64)        \
                                             : (w2h + (size_t)(row-128)*64);  \
            const uint32_t* sl = (row < 128) ? (w1l + (size_t)row * 64)        \
                                             : (w2l + (size_t)(row-128)*64);  \
            cpa16(s0 + 2 * ZT_X * 4 + off,          sh + f4 * 4);              \
            cpa16(s0 + (2 * ZT_X + ZT_W) * 4 + off, sl + f4 * 4);              \
        }                                                                      \
        CP_COMMIT();                                                           \
    }

    Z_LDGX(0);
    Z_CPAW(0, 0);
    for (int c = 0; c < C; c++) {
        const int sc = c & 1;
        Z_STSX(sc);
        if (c + 1 < C) { Z_LDGX(c + 1); Z_CPAW(c + 1, (c + 1) & 1); CP_WAIT1(); }
        else           { CP_WAIT0(); }
        __syncthreads();
        const uint32_t* Xh = su + sc * ZS_W;
        const uint32_t* Xl = Xh + ZT_X;
        const uint32_t* Wh = Xh + 2 * ZT_X;
        const uint32_t* Wl = Wh + ZT_W;
        uint32_t ah[2][4], al[2][4], bh[4][2], bl[4][2];
#pragma unroll
        for (int mf = 0; mf < 2; mf++) {
            const int r = mf * 16 + g;
            ah[mf][0] = Xh[r * 12 + tq];
            ah[mf][1] = Xh[(r + 8) * 12 + tq];
            ah[mf][2] = Xh[r * 12 + tq + 4];
            ah[mf][3] = Xh[(r + 8) * 12 + tq + 4];
            al[mf][0] = Xl[r * 12 + tq];
            al[mf][1] = Xl[(r + 8) * 12 + tq];
            al[mf][2] = Xl[r * 12 + tq + 4];
            al[mf][3] = Xl[(r + 8) * 12 + tq + 4];
        }
#pragma unroll
        for (int nf = 0; nf < 4; nf++) {
            const int cj = wj * 32 + nf * 8 + g;
            bh[nf][0] = Wh[cj * 12 + tq];
            bh[nf][1] = Wh[cj * 12 + tq + 4];
            bl[nf][0] = Wl[cj * 12 + tq];
            bl[nf][1] = Wl[cj * 12 + tq + 4];
        }
#pragma unroll
        for (int nf = 0; nf < 4; nf++)
#pragma unroll
            for (int mf = 0; mf < 2; mf++) mma16(acc[mf][nf], ah[mf], bh[nf]);
#pragma unroll
        for (int nf = 0; nf < 4; nf++)
#pragma unroll
            for (int mf = 0; mf < 2; mf++) mma16(acc[mf][nf], al[mf], bh[nf]);
#pragma unroll
        for (int nf = 0; nf < 4; nf++)
#pragma unroll
            for (int mf = 0; mf < 2; mf++) mma16(acc[mf][nf], ah[mf], bl[nf]);
        __syncthreads();
    }
#undef Z_LDGX
#undef Z_STSX
#undef Z_CPAW

#pragma unroll
    for (int mf = 0; mf < 2; mf++) {
#pragma unroll
        for (int h2 = 0; h2 < 2; h2++) {
            const int i = i0 + mf * 16 + g + h2 * 8;
            const size_t rb = (size_t)i * HQ;
#pragma unroll
            for (int nf = 0; nf < 4; nf++) {
                const int j = wj * 32 + nf * 8 + 2 * tq;
                if (wj < 4) {
                    const float2 bb1 = *reinterpret_cast<const float2*>(b_wz + j);
                    const float2 bb2 = *reinterpret_cast<const float2*>(b_uz + j);
                    float v0 = acc[mf][nf][h2 * 2 + 0] + bb1.x + bb2.x;
                    float v1 = acc[mf][nf][h2 * 2 + 1] + bb1.y + bb2.y;
                    float2 o;
                    o.x = 1.f / (1.f + __expf(-v0));
                    o.y = 1.f / (1.f + __expf(-v1));
                    *reinterpret_cast<float2*>(zout + rb + j) = o;
                } else {
                    const int jj = j - 128;
                    const float2 bb1 = *reinterpret_cast<const float2*>(b_wr + jj);
                    const float2 bb2 = *reinterpret_cast<const float2*>(b_ur + jj);
                    float v0 = acc[mf][nf][h2 * 2 + 0] + bb1.x + bb2.x;
                    float v1 = acc[mf][nf][h2 * 2 + 1] + bb1.y + bb2.y;
                    const float2 hv = *reinterpret_cast<const float2*>(hp + rb + jj);
                    float2 o;
                    o.x = hv.x * (1.f / (1.f + __expf(-v0)));
                    o.y = hv.y * (1.f / (1.f + __expf(-v1)));
                    *reinterpret_cast<float2*>(rhout + rb + jj) = o;
                }
            }
        }
    }
}

// ---------------------------------------------------------------------------
// c-gate: D = a@w^T + rh@u^T (+b); h' = (1-z)h + z tanh(D)
// CTA 64 rows x 128 cols (acc 32/thread). 8 warps, warp tile 64x16 (mf=4,nf=2).
// stage: Xh/Xl 64x12=768 w each, Wh/Wl 128x12=1536 w each = 4608 w; x2 = 36864 B.
// ---------------------------------------------------------------------------
#define GT_X 768             // 64*12
#define GT_W 1536            // 128*12
#define GS_W 4608
__global__ __launch_bounds__(256)
void k_cgate(const float* __restrict__ ap, const float* __restrict__ rhp,
             const uint32_t* __restrict__ Wsp,
             const float* __restrict__ b1, const float* __restrict__ b2,
             const float* __restrict__ hp, const float* __restrict__ zp,
             float* __restrict__ outp)
{
    extern __shared__ uint32_t su[];
    const uint32_t sb = smem_u32(su);
    const int t = threadIdx.x, lane = t & 31, wj = t >> 5;
    const int g = lane >> 2, tq = lane & 3;
    const int i0 = blockIdx.x * 64;
    const int SW = HQ * HQ / 2;

    float acc[4][2][4];
#pragma unroll
    for (int a_ = 0; a_ < 4; a_++)
#pragma unroll
        for (int b_ = 0; b_ < 2; b_++)
#pragma unroll
            for (int c_ = 0; c_ < 4; c_++) acc[a_][b_][c_] = 0.f;

    const int C = 16;
    float4 rX;
    const int xrow = t >> 2, xf4 = t & 3;   // 256 threads: 64 rows x 4 f4

#define G_LDGX(cc)                                                             \
    {                                                                          \
        const int gg = (cc) >> 3;                                              \
        const int kc = ((cc) & 7) * 16;                                        \
        const float* xp = (gg ? rhp : ap) + (size_t)i0 * HQ + kc;              \
        rX = *reinterpret_cast<const float4*>(xp + (size_t)xrow*HQ + xf4*4);   \
    }
#define G_STSX(st)                                                             \
    {                                                                          \
        uint32_t* s0 = su + (st) * GS_W;                                       \
        const int off = xrow * 12 + xf4 * 2;                                   \
        uint2 H, L;                                                            \
        hsplit2(rX.x, rX.y, H.x, L.x);                                         \
        hsplit2(rX.z, rX.w, H.y, L.y);                                         \
        *reinterpret_cast<uint2*>(s0 + off) = H;                               \
        *reinterpret_cast<uint2*>(s0 + GT_X + off) = L;                        \
    }
#define G_CPAW(cc, st)                                                         \
    {                                                                          \
        const int gg = (cc) >> 3;                                              \
        const int kw = ((cc) & 7) * 8;                                         \
        const uint32_t* wh_ = Wsp + (gg ? 10 : 8) * SW + kw;                   \
        const uint32_t* wl_ = Wsp + (gg ? 11 : 9) * SW + kw;                   \
        const uint32_t s0 = sb + (uint32_t)(st) * GS_W * 4;                    \
        {                                                                      \
            const int row = t >> 1, f4 = t & 1;                                \
            const uint32_t off = (uint32_t)(row * 12 + f4 * 4) * 4;            \
            cpa16(s0 + 2 * GT_X * 4 + off, wh_ + (size_t)row * 64 + f4 * 4);   \
            cpa16(s0 + (2 * GT_X + GT_W) * 4 + off,                            \
                  wl_ + (size_t)row * 64 + f4 * 4);                            \
        }                                                                      \
        CP_COMMIT();                                                           \
    }

    G_LDGX(0);
    G_CPAW(0, 0);
    for (int c = 0; c < C; c++) {
        const int sc = c & 1;
        G_STSX(sc);
        if (c + 1 < C) { G_LDGX(c + 1); G_CPAW(c + 1, (c + 1) & 1); CP_WAIT1(); }
        else           { CP_WAIT0(); }
        __syncthreads();
        const uint32_t* Xh = su + sc * GS_W;
        const uint32_t* Xl = Xh + GT_X;
        const uint32_t* Wh = Xh + 2 * GT_X;
        const uint32_t* Wl = Wh + GT_W;
        uint32_t ah[4][4], al[4][4], bh[2][2], bl[2][2];
#pragma unroll
        for (int mf = 0; mf < 4; mf++) {
            const int r = mf * 16 + g;
            ah[mf][0] = Xh[r * 12 + tq];
            ah[mf][1] = Xh[(r + 8) * 12 + tq];
            ah[mf][2] = Xh[r * 12 + tq + 4];
            ah[mf][3] = Xh[(r + 8) * 12 + tq + 4];
            al[mf][0] = Xl[r * 12 + tq];
            al[mf][1] = Xl[(r + 8) * 12 + tq];
            al[mf][2] = Xl[r * 12 + tq + 4];
            al[mf][3] = Xl[(r + 8) * 12 + tq + 4];
        }
#pragma unroll
        for (int nf = 0; nf < 2; nf++) {
            const int cj = wj * 16 + nf * 8 + g;
            bh[nf][0] = Wh[cj * 12 + tq];
            bh[nf][1] = Wh[cj * 12 + tq + 4];
            bl[nf][0] = Wl[cj * 12 + tq];
            bl[nf][1] = Wl[cj * 12 + tq + 4];
        }
#pragma unroll
        for (int nf = 0; nf < 2; nf++)
#pragma unroll
            for (int mf = 0; mf < 4; mf++) mma16(acc[mf][nf], ah[mf], bh[nf]);
#pragma unroll
        for (int nf = 0; nf < 2; nf++)
#pragma unroll
            for (int mf = 0; mf < 4; mf++) mma16(acc[mf][nf], al[mf], bh[nf]);
#pragma unroll
        for (int nf = 0; nf < 2; nf++)
#pragma unroll
            for (int mf = 0; mf < 4; mf++) mma16(acc[mf][nf], ah[mf], bl[nf]);
        __syncthreads();
    }
#undef G_LDGX
#undef G_STSX
#undef G_CPAW

#pragma unroll
    for (int mf = 0; mf < 4; mf++) {
#pragma unroll
        for (int h2 = 0; h2 < 2; h2++) {
            const int i = i0 + mf * 16 + g + h2 * 8;
            const size_t rb = (size_t)i * HQ;
#pragma unroll
            for (int nf = 0; nf < 2; nf++) {
                const int j = wj * 16 + nf * 8 + 2 * tq;
                const float2 bb1 = *reinterpret_cast<const float2*>(b1 + j);
                const float2 bb2 = *reinterpret_cast<const float2*>(b2 + j);
                float v0 = acc[mf][nf][h2 * 2 + 0] + bb1.x + bb2.x;
                float v1 = acc[mf][nf][h2 * 2 + 1] + bb1.y + bb2.y;
                const float2 hv = *reinterpret_cast<const float2*>(hp + rb + j);
                const float2 zz = *reinterpret_cast<const float2*>(zp + rb + j);
                float2 o;
                o.x = (1.f - zz.x) * hv.x + zz.x * tanhf(v0);
                o.y = (1.f - zz.y) * hv.y + zz.y * tanhf(v1);
                *reinterpret_cast<float2*>(outp + rb + j) = o;
            }
        }
    }
}

// ---------------------------------------------------------------------------
// Host launcher
// ---------------------------------------------------------------------------
extern "C" void kernel_launch(void* const* d_in, const int* in_sizes, int n_in,
                              void* d_out, int out_size)
{
    const float* A      = (const float*)d_in[0];
    const float* hidden = (const float*)d_in[1];
    const float* b_ah   = (const float*)d_in[2];
    const float* w_z    = (const float*)d_in[3];
    const float* b_wz   = (const float*)d_in[4];
    const float* u_z    = (const float*)d_in[5];
    const float* b_uz   = (const float*)d_in[6];
    const float* w_r    = (const float*)d_in[7];
    const float* b_wr   = (const float*)d_in[8];
    const float* u_r    = (const float*)d_in[9];
    const float* b_ur   = (const float*)d_in[10];
    const float* w      = (const float*)d_in[11];
    const float* b_w    = (const float*)d_in[12];
    const float* u      = (const float*)d_in[13];
    const float* b_u    = (const float*)d_in[14];
    float* out = (float*)d_out;

    float *ga, *gz, *grh, *h0, *h1;
    uint32_t* Wsp;
    cudaGetSymbolAddress((void**)&ga,  g_a);
    cudaGetSymbolAddress((void**)&gz,  g_z);
    cudaGetSymbolAddress((void**)&grh, g_rh);
    cudaGetSymbolAddress((void**)&h0,  g_h0);
    cudaGetSymbolAddress((void**)&h1,  g_h1);
    cudaGetSymbolAddress((void**)&Wsp, g_Wh);

    cudaFuncSetAttribute(k_mma_a, cudaFuncAttributeMaxDynamicSharedMemorySize, 34816);
    cudaFuncSetAttribute(k_zr,    cudaFuncAttributeMaxDynamicSharedMemorySize, 55296);
    cudaFuncSetAttribute(k_cgate, cudaFuncAttributeMaxDynamicSharedMemorySize, 36864);

    // one fused weight-split launch: grid.y = matrix index 0..5
    k_splith6<<<dim3(16, 6), 256>>>(w_z, u_z, w_r, u_r, w, u, Wsp);

    const float* hpr[4] = { hidden, h0, h1, h0 };
    float*       hnr[4] = { h0, h1, h0, out };

    for (int s = 0; s < 4; s++) {
        const float* hp = hpr[s];
        k_mma_a<<<dim3(4, BQ), 256, 34816>>>(A, hp, b_ah, ga);
        k_zr<<<M2 / 32, 256, 55296>>>(ga, hp, Wsp, b_wz, b_uz, b_wr, b_ur, gz, grh);
        k_cgate<<<M2 / 64, 256, 36864>>>(ga, grh, Wsp, b_w, b_u, hp, gz, hnr[s]);
    }
}

// round 15
// speedup vs baseline: 1.8164x; 1.7457x over previous
#include <cuda_runtime.h>
#include <cuda_fp16.h>
#include <math.h>
#include <stdint.h>

#define BQ 128
#define NQ 512
#define HQ 128
#define M2 65536

// ---------------- scratch (allocation-free rule) ----------------
__device__ float    g_a [(size_t)M2 * HQ];
__device__ float    g_z [(size_t)M2 * HQ];
__device__ float    g_rh[(size_t)M2 * HQ];
__device__ float    g_h0[(size_t)M2 * HQ];
__device__ float    g_h1[(size_t)M2 * HQ];
__device__ uint32_t g_Wh[12 * (size_t)HQ * HQ / 2];  // packed half2 k-pairs:
// [0,1]=wz(hi,lo) [2,3]=uz [4,5]=wr [6,7]=ur [8,9]=w [10,11]=u ; each 8192 words

// ---------------- helpers ----------------
__device__ __forceinline__ void cpa16(uint32_t dst, const void* src) {
    asm volatile("cp.async.cg.shared.global [%0], [%1], 16;" :: "r"(dst), "l"(src));
}
#define CP_COMMIT() asm volatile("cp.async.commit_group;" ::: "memory")
#define CP_WAIT1()  asm volatile("cp.async.wait_group 1;" ::: "memory")
#define CP_WAIT0()  asm volatile("cp.async.wait_group 0;" ::: "memory")

__device__ __forceinline__ uint32_t smem_u32(const void* p) {
    uint32_t a;
    asm("{ .reg .u64 t; cvta.to.shared.u64 t, %1; cvt.u32.u64 %0, t; }" : "=r"(a) : "l"(p));
    return a;
}
// Split (x,y) into packed fp16 hi pair + fp16 residual pair (Markidis split).
__device__ __forceinline__ void hsplit2(float x, float y, uint32_t& hi, uint32_t& lo) {
    __half hx = __float2half_rn(x);
    __half hy = __float2half_rn(y);
    __half lx = __float2half_rn(x - __half2float(hx));
    __half ly = __float2half_rn(y - __half2float(hy));
    __half2 H = __halves2half2(hx, hy);
    __half2 L = __halves2half2(lx, ly);
    hi = *reinterpret_cast<uint32_t*>(&H);
    lo = *reinterpret_cast<uint32_t*>(&L);
}
__device__ __forceinline__ void mma16(float* c, const uint32_t* a, const uint32_t* b) {
    asm volatile(
        "mma.sync.aligned.m16n8k16.row.col.f32.f16.f16.f32 "
        "{%0,%1,%2,%3}, {%4,%5,%6,%7}, {%8,%9}, {%0,%1,%2,%3};"
        : "+f"(c[0]), "+f"(c[1]), "+f"(c[2]), "+f"(c[3])
        : "r"(a[0]), "r"(a[1]), "r"(a[2]), "r"(a[3]), "r"(b[0]), "r"(b[1]));
}
#define LDSM4(r0, r1, r2, r3, a)                                               \
    asm volatile("ldmatrix.sync.aligned.m8n8.x4.shared.b16 {%0,%1,%2,%3}, [%4];" \
                 : "=r"(r0), "=r"(r1), "=r"(r2), "=r"(r3) : "r"(a))

// ---------------------------------------------------------------------------
// Weight split pre-pass (fused: all 6 matrices in one launch via blockIdx.y)
// ---------------------------------------------------------------------------
__global__ __launch_bounds__(256)
void k_splith6(const float* __restrict__ s0, const float* __restrict__ s1,
               const float* __restrict__ s2, const float* __restrict__ s3,
               const float* __restrict__ s4, const float* __restrict__ s5,
               uint32_t* __restrict__ Wsp)
{
    const int m = blockIdx.y;
    const float* srcs[6] = { s0, s1, s2, s3, s4, s5 };
    const float* s = srcs[m];
    const int SW = HQ * HQ / 2;
    uint32_t* hi = Wsp + (size_t)(2 * m) * SW;
    uint32_t* lo = Wsp + (size_t)(2 * m + 1) * SW;
    int i = blockIdx.x * blockDim.x + threadIdx.x;    // float4 index, 4096 total
    float4 v = reinterpret_cast<const float4*>(s)[i];
    uint32_t h0, l0, h1, l1;
    hsplit2(v.x, v.y, h0, l0);
    hsplit2(v.z, v.w, h1, l1);
    uint2 H; H.x = h0; H.y = h1;
    uint2 L; L.x = l0; L.y = l1;
    reinterpret_cast<uint2*>(hi)[i] = H;
    reinterpret_cast<uint2*>(lo)[i] = L;
}

// ---------------------------------------------------------------------------
// a-GEMM: a[b,n,h] = sum_m A[b,m,n]*h[b,m,h] + bias[h]  (raw fp32 in/out)
// UNCHANGED from round-9 best (1120us). K-major smem stride 136 w, K-chunk 16.
// ---------------------------------------------------------------------------
#define AT_W 1088            // words per tile (8*136)
#define AS_W 4352            // words per stage (4 tiles)
__global__ __launch_bounds__(256)
void k_mma_a(const float* __restrict__ A, const float* __restrict__ Hp,
             const float* __restrict__ bias, float* __restrict__ outp)
{
    extern __shared__ uint32_t su[];
    const int t = threadIdx.x, lane = t & 31, wid = t >> 5;
    const int wi = wid & 1, wj = wid >> 1;
    const int g = lane >> 2, tq = lane & 3;
    const int b = blockIdx.y, n0 = blockIdx.x * 128;

    const float* Ab = A  + (size_t)b * NQ * NQ + n0;
    const float* Hb = Hp + (size_t)b * NQ * HQ;

    float acc[4][4][4];
#pragma unroll
    for (int a_ = 0; a_ < 4; a_++)
#pragma unroll
        for (int b_ = 0; b_ < 4; b_++)
#pragma unroll
            for (int c_ = 0; c_ < 4; c_++) acc[a_][b_][c_] = 0.f;

    const int C = 32;
    const int kp = t >> 5;       // 0..7 (k-pair within chunk)
    const int c4 = t & 31;       // float4 col index 0..31
    float4 rA0, rA1, rH0, rH1;

#define A_LDG(cc)                                                              \
    {                                                                          \
        const int m0 = (cc) * 16 + kp * 2;                                     \
        rA0 = *reinterpret_cast<const float4*>(Ab + (size_t)m0 * NQ + c4 * 4); \
        rA1 = *reinterpret_cast<const float4*>(Ab + (size_t)(m0+1)*NQ + c4*4); \
        rH0 = *reinterpret_cast<const float4*>(Hb + (size_t)m0 * HQ + c4 * 4); \
        rH1 = *reinterpret_cast<const float4*>(Hb + (size_t)(m0+1)*HQ + c4*4); \
    }
#define A_STS(st)                                                              \
    {                                                                          \
        uint32_t* s0 = su + (st) * AS_W;                                       \
        const int off = kp * 136 + c4 * 4;                                     \
        uint4 H, L;                                                            \
        hsplit2(rA0.x, rA1.x, H.x, L.x); hsplit2(rA0.y, rA1.y, H.y, L.y);      \
        hsplit2(rA0.z, rA1.z, H.z, L.z); hsplit2(rA0.w, rA1.w, H.w, L.w);      \
        *reinterpret_cast<uint4*>(s0 + off) = H;                               \
        *reinterpret_cast<uint4*>(s0 + AT_W + off) = L;                        \
        hsplit2(rH0.x, rH1.x, H.x, L.x); hsplit2(rH0.y, rH1.y, H.y, L.y);      \
        hsplit2(rH0.z, rH1.z, H.z, L.z); hsplit2(rH0.w, rH1.w, H.w, L.w);      \
        *reinterpret_cast<uint4*>(s0 + 2 * AT_W + off) = H;                    \
        *reinterpret_cast<uint4*>(s0 + 3 * AT_W + off) = L;                    \
    }

    A_LDG(0);
    for (int c = 0; c < C; c++) {
        const int sc = c & 1;
        A_STS(sc);
        if (c + 1 < C) A_LDG(c + 1);
        __syncthreads();
        const uint32_t* Xh = su + sc * AS_W;
        const uint32_t* Xl = Xh + AT_W;
        const uint32_t* Wh = Xh + 2 * AT_W;
        const uint32_t* Wl = Xh + 3 * AT_W;
        uint32_t ah[4][4], al[4][4], bh[4][2], bl[4][2];
#pragma unroll
        for (int mf = 0; mf < 4; mf++) {
            const int r = wi * 64 + mf * 16 + g;
            ah[mf][0] = Xh[tq * 136 + r];
            ah[mf][1] = Xh[tq * 136 + r + 8];
            ah[mf][2] = Xh[(tq + 4) * 136 + r];
            ah[mf][3] = Xh[(tq + 4) * 136 + r + 8];
            al[mf][0] = Xl[tq * 136 + r];
            al[mf][1] = Xl[tq * 136 + r + 8];
            al[mf][2] = Xl[(tq + 4) * 136 + r];
            al[mf][3] = Xl[(tq + 4) * 136 + r + 8];
        }
#pragma unroll
        for (int nf = 0; nf < 4; nf++) {
            const int cj = wj * 32 + nf * 8 + g;
            bh[nf][0] = Wh[tq * 136 + cj];
            bh[nf][1] = Wh[(tq + 4) * 136 + cj];
            bl[nf][0] = Wl[tq * 136 + cj];
            bl[nf][1] = Wl[(tq + 4) * 136 + cj];
        }
#pragma unroll
        for (int nf = 0; nf < 4; nf++)
#pragma unroll
            for (int mf = 0; mf < 4; mf++) mma16(acc[mf][nf], ah[mf], bh[nf]);
#pragma unroll
        for (int nf = 0; nf < 4; nf++)
#pragma unroll
            for (int mf = 0; mf < 4; mf++) mma16(acc[mf][nf], al[mf], bh[nf]);
#pragma unroll
        for (int nf = 0; nf < 4; nf++)
#pragma unroll
            for (int mf = 0; mf < 4; mf++) mma16(acc[mf][nf], ah[mf], bl[nf]);
        __syncthreads();
    }
#undef A_LDG
#undef A_STS

    const size_t obase = (size_t)b * NQ * HQ;
#pragma unroll
    for (int mf = 0; mf < 4; mf++) {
#pragma unroll
        for (int h2 = 0; h2 < 2; h2++) {
            const int i = n0 + wi * 64 + mf * 16 + g + h2 * 8;
            const size_t rb = obase + (size_t)i * HQ;
#pragma unroll
            for (int nf = 0; nf < 4; nf++) {
                const int j = wj * 32 + nf * 8 + 2 * tq;
                const float2 bb = *reinterpret_cast<const float2*>(bias + j);
                float2 v;
                v.x = acc[mf][nf][h2 * 2 + 0] + bb.x;
                v.y = acc[mf][nf][h2 * 2 + 1] + bb.y;
                *reinterpret_cast<float2*>(outp + rb + j) = v;
            }
        }
    }
}

// ---------------------------------------------------------------------------
// Fused z+r: [z|r] = a@[wz|wr]^T + h@[uz|ur]^T (+biases)
// ROUND-9 structure (CTA 64x256, warp 64x32); fragment loads now via LDSM.
// M-major smem [i][kpair], stride 12. 2-stage. smem 61440 B.
// ---------------------------------------------------------------------------
#define ZT_X 768             // 64*12
#define ZT_W 3072            // 256*12
#define ZS_W 7680
__global__ __launch_bounds__(256)
void k_zr(const float* __restrict__ ap, const float* __restrict__ hp,
          const uint32_t* __restrict__ Wsp,
          const float* __restrict__ b_wz, const float* __restrict__ b_uz,
          const float* __restrict__ b_wr, const float* __restrict__ b_ur,
          float* __restrict__ zout, float* __restrict__ rhout)
{
    extern __shared__ uint32_t su[];
    const uint32_t sb = smem_u32(su);
    const int t = threadIdx.x, lane = t & 31, wj = t >> 5;
    const int g = lane >> 2, tq = lane & 3;
    const int i0 = blockIdx.x * 64;
    const int SW = HQ * HQ / 2;   // 8192 packed words per matrix
    // LDSM lane->address offsets (words), stride-12 rows
    const int xo = ((lane & 7) + ((lane >> 3) & 1) * 8) * 12 + ((lane >> 4) & 1) * 4;
    const int wo = ((lane & 7) + ((lane >> 4) & 1) * 8) * 12 + ((lane >> 3) & 1) * 4;

    float acc[4][4][4];
#pragma unroll
    for (int a_ = 0; a_ < 4; a_++)
#pragma unroll
        for (int b_ = 0; b_ < 4; b_++)
#pragma unroll
            for (int c_ = 0; c_ < 4; c_++) acc[a_][b_][c_] = 0.f;

    const int C = 16;
    float4 rX;
    const int xrow = t >> 2, xf4 = t & 3;

#define Z_LDGX(cc)                                                             \
    {                                                                          \
        const int half = (cc) >> 3;                                            \
        const int kc = ((cc) & 7) * 16;                                        \
        const float* xp = (half ? hp : ap) + (size_t)i0 * HQ + kc;             \
        rX = *reinterpret_cast<const float4*>(xp + (size_t)xrow*HQ + xf4*4);   \
    }
#define Z_STSX(st)                                                             \
    {                                                                          \
        uint32_t* s0 = su + (st) * ZS_W;                                       \
        const int off = xrow * 12 + xf4 * 2;                                   \
        uint2 H, L;                                                            \
        hsplit2(rX.x, rX.y, H.x, L.x);                                         \
        hsplit2(rX.z, rX.w, H.y, L.y);                                         \
        *reinterpret_cast<uint2*>(s0 + off) = H;                               \
        *reinterpret_cast<uint2*>(s0 + ZT_X + off) = L;                        \
    }
#define Z_CPAW(cc, st)                                                         \
    {                                                                          \
        const int half = (cc) >> 3;                                            \
        const int kw = ((cc) & 7) * 8;                                         \
        const uint32_t* w1h = Wsp + (half ? 2 : 0) * SW + kw;                  \
        const uint32_t* w1l = Wsp + (half ? 3 : 1) * SW + kw;                  \
        const uint32_t* w2h = Wsp + (half ? 6 : 4) * SW + kw;                  \
        const uint32_t* w2l = Wsp + (half ? 7 : 5) * SW + kw;                  \
        const uint32_t s0 = sb + (uint32_t)(st) * ZS_W * 4;                    \
        _Pragma("unroll")                                                      \
        for (int p = 0; p < 2; p++) {                                          \
            const int idx = t + p * 256;                                       \
            const int row = idx >> 1, f4 = idx & 1;                            \
            const uint32_t off = (uint32_t)(row * 12 + f4 * 4) * 4;            \
            const uint32_t* sh = (row < 128) ? (w1h + (size_t)row * 64)        \
                                             : (w2h + (size_t)(row-128)*64);  \
            const uint32_t* sl = (row < 128) ? (w1l + (size_t)row * 64)        \
                                             : (w2l + (size_t)(row-128)*64);  \
            cpa16(s0 + 2 * ZT_X * 4 + off,          sh + f4 * 4);              \
            cpa16(s0 + (2 * ZT_X + ZT_W) * 4 + off, sl + f4 * 4);              \
        }                                                                      \
        CP_COMMIT();                                                           \
    }

    Z_LDGX(0);
    Z_CPAW(0, 0);
    for (int c = 0; c < C; c++) {
        const int sc = c & 1;
        Z_STSX(sc);
        if (c + 1 < C) { Z_LDGX(c + 1); Z_CPAW(c + 1, (c + 1) & 1); CP_WAIT1(); }
        else           { CP_WAIT0(); }
        __syncthreads();
        const uint32_t xb = sb + (uint32_t)sc * ZS_W * 4;
        const uint32_t wb = xb + 2 * ZT_X * 4;
        uint32_t ah[4][4], al[4][4], bh[4][2], bl[4][2];
#pragma unroll
        for (int mf = 0; mf < 4; mf++) {
            const uint32_t axy = xb + (uint32_t)(mf * 16 * 12 + xo) * 4;
            LDSM4(ah[mf][0], ah[mf][1], ah[mf][2], ah[mf][3], axy);
            LDSM4(al[mf][0], al[mf][1], al[mf][2], al[mf][3], axy + ZT_X * 4);
        }
#pragma unroll
        for (int p = 0; p < 2; p++) {
            const uint32_t bxy = wb + (uint32_t)((wj * 32 + p * 16) * 12 + wo) * 4;
            LDSM4(bh[2*p][0], bh[2*p][1], bh[2*p+1][0], bh[2*p+1][1], bxy);
            LDSM4(bl[2*p][0], bl[2*p][1], bl[2*p+1][0], bl[2*p+1][1], bxy + ZT_W * 4);
        }
#pragma unroll
        for (int nf = 0; nf < 4; nf++)
#pragma unroll
            for (int mf = 0; mf < 4; mf++) mma16(acc[mf][nf], ah[mf], bh[nf]);
#pragma unroll
        for (int nf = 0; nf < 4; nf++)
#pragma unroll
            for (int mf = 0; mf < 4; mf++) mma16(acc[mf][nf], al[mf], bh[nf]);
#pragma unroll
        for (int nf = 0; nf < 4; nf++)
#pragma unroll
            for (int mf = 0; mf < 4; mf++) mma16(acc[mf][nf], ah[mf], bl[nf]);
        __syncthreads();
    }
#undef Z_LDGX
#undef Z_STSX
#undef Z_CPAW

#pragma unroll
    for (int mf = 0; mf < 4; mf++) {
#pragma unroll
        for (int h2 = 0; h2 < 2; h2++) {
            const int i = i0 + mf * 16 + g + h2 * 8;
            const size_t rb = (size_t)i * HQ;
#pragma unroll
            for (int nf = 0; nf < 4; nf++) {
                const int j = wj * 32 + nf * 8 + 2 * tq;
                if (wj < 4) {
                    const float2 bb1 = *reinterpret_cast<const float2*>(b_wz + j);
                    const float2 bb2 = *reinterpret_cast<const float2*>(b_uz + j);
                    float v0 = acc[mf][nf][h2 * 2 + 0] + bb1.x + bb2.x;
                    float v1 = acc[mf][nf][h2 * 2 + 1] + bb1.y + bb2.y;
                    float2 o;
                    o.x = 1.f / (1.f + __expf(-v0));
                    o.y = 1.f / (1.f + __expf(-v1));
                    *reinterpret_cast<float2*>(zout + rb + j) = o;
                } else {
                    const int jj = j - 128;
                    const float2 bb1 = *reinterpret_cast<const float2*>(b_wr + jj);
                    const float2 bb2 = *reinterpret_cast<const float2*>(b_ur + jj);
                    float v0 = acc[mf][nf][h2 * 2 + 0] + bb1.x + bb2.x;
                    float v1 = acc[mf][nf][h2 * 2 + 1] + bb1.y + bb2.y;
                    const float2 hv = *reinterpret_cast<const float2*>(hp + rb + jj);
                    float2 o;
                    o.x = hv.x * (1.f / (1.f + __expf(-v0)));
                    o.y = hv.y * (1.f / (1.f + __expf(-v1)));
                    *reinterpret_cast<float2*>(rhout + rb + jj) = o;
                }
            }
        }
    }
}

// ---------------------------------------------------------------------------
// c-gate: D = a@w^T + rh@u^T (+b); h' = (1-z)h + z tanh(D)
// ROUND-9 structure (CTA 128x128, warp 64x32); fragment loads now via LDSM.
// M-major smem [i][kpair] stride 12, K-chunk 16, C=16, 2-stage. smem 49152 B.
// ---------------------------------------------------------------------------
#define GT_W 1536
#define GS_W 6144
__global__ __launch_bounds__(256)
void k_cgate(const float* __restrict__ ap, const float* __restrict__ rhp,
             const uint32_t* __restrict__ Wsp,
             const float* __restrict__ b1, const float* __restrict__ b2,
             const float* __restrict__ hp, const float* __restrict__ zp,
             float* __restrict__ outp)
{
    extern __shared__ uint32_t su[];
    const uint32_t sb = smem_u32(su);
    const int t = threadIdx.x, lane = t & 31, wid = t >> 5;
    const int wi = wid & 1, wj = wid >> 1;
    const int g = lane >> 2, tq = lane & 3;
    const int i0 = blockIdx.x * 128;
    const int SW = HQ * HQ / 2;
    const int xo = ((lane & 7) + ((lane >> 3) & 1) * 8) * 12 + ((lane >> 4) & 1) * 4;
    const int wo = ((lane & 7) + ((lane >> 4) & 1) * 8) * 12 + ((lane >> 3) & 1) * 4;

    float acc[4][4][4];
#pragma unroll
    for (int a_ = 0; a_ < 4; a_++)
#pragma unroll
        for (int b_ = 0; b_ < 4; b_++)
#pragma unroll
            for (int c_ = 0; c_ < 4; c_++) acc[a_][b_][c_] = 0.f;

    const int C = 16;
    float4 rX[2];

#define G_LDGX(cc)                                                             \
    {                                                                          \
        const int gg = (cc) >> 3;                                              \
        const int kc = ((cc) & 7) * 16;                                        \
        const float* xp = (gg ? rhp : ap) + (size_t)i0 * HQ + kc;              \
        _Pragma("unroll")                                                      \
        for (int p = 0; p < 2; p++) {                                          \
            const int idx = t + p * 256;                                       \
            const int row = idx >> 2, f4 = idx & 3;                            \
            rX[p] = *reinterpret_cast<const float4*>(                          \
                xp + (size_t)row * HQ + f4 * 4);                               \
        }                                                                      \
    }
#define G_STSX(st)                                                             \
    {                                                                          \
        uint32_t* s0 = su + (st) * GS_W;                                       \
        _Pragma("unroll")                                                      \
        for (int p = 0; p < 2; p++) {                                          \
            const int idx = t + p * 256;                                       \
            const int row = idx >> 2, f4 = idx & 3;                            \
            const int off = row * 12 + f4 * 2;                                 \
            uint2 H, L;                                                        \
            hsplit2(rX[p].x, rX[p].y, H.x, L.x);                               \
            hsplit2(rX[p].z, rX[p].w, H.y, L.y);                               \
            *reinterpret_cast<uint2*>(s0 + off) = H;                           \
            *reinterpret_cast<uint2*>(s0 + GT_W + off) = L;                    \
        }                                                                      \
    }
#define G_CPAW(cc, st)                                                         \
    {                                                                          \
        const int gg = (cc) >> 3;                                              \
        const int kw = ((cc) & 7) * 8;                                         \
        const uint32_t* wh_ = Wsp + (gg ? 10 : 8) * SW + kw;                   \
        const uint32_t* wl_ = Wsp + (gg ? 11 : 9) * SW + kw;                   \
        const uint32_t s0 = sb + (uint32_t)(st) * GS_W * 4;                    \
        {                                                                      \
            const int row = t >> 1, f4 = t & 1;                                \
            const uint32_t off = (uint32_t)(row * 12 + f4 * 4) * 4;            \
            cpa16(s0 + 2 * GT_W * 4 + off, wh_ + (size_t)row * 64 + f4 * 4);   \
            cpa16(s0 + 3 * GT_W * 4 + off, wl_ + (size_t)row * 64 + f4 * 4);   \
        }                                                                      \
        CP_COMMIT();                                                           \
    }

    G_LDGX(0);
    G_CPAW(0, 0);
    for (int c = 0; c < C; c++) {
        const int sc = c & 1;
        G_STSX(sc);
        if (c + 1 < C) { G_LDGX(c + 1); G_CPAW(c + 1, (c + 1) & 1); CP_WAIT1(); }
        else           { CP_WAIT0(); }
        __syncthreads();
        const uint32_t xb = sb + (uint32_t)sc * GS_W * 4;
        const uint32_t wb = xb + 2 * GT_W * 4;
        uint32_t ah[4][4], al[4][4], bh[4][2], bl[4][2];
#pragma unroll
        for (int mf = 0; mf < 4; mf++) {
            const uint32_t axy = xb + (uint32_t)((wi * 64 + mf * 16) * 12 + xo) * 4;
            LDSM4(ah[mf][0], ah[mf][1], ah[mf][2], ah[mf][3], axy);
            LDSM4(al[mf][0], al[mf][1], al[mf][2], al[mf][3], axy + GT_W * 4);
        }
#pragma unroll
        for (int p = 0; p < 2; p++) {
            const uint32_t bxy = wb + (uint32_t)((wj * 32 + p * 16) * 12 + wo) * 4;
            LDSM4(bh[2*p][0], bh[2*p][1], bh[2*p+1][0], bh[2*p+1][1], bxy);
            LDSM4(bl[2*p][0], bl[2*p][1], bl[2*p+1][0], bl[2*p+1][1], bxy + GT_W * 4);
        }
#pragma unroll
        for (int nf = 0; nf < 4; nf++)
#pragma unroll
            for (int mf = 0; mf < 4; mf++) mma16(acc[mf][nf], ah[mf], bh[nf]);
#pragma unroll
        for (int nf = 0; nf < 4; nf++)
#pragma unroll
            for (int mf = 0; mf < 4; mf++) mma16(acc[mf][nf], al[mf], bh[nf]);
#pragma unroll
        for (int nf = 0; nf < 4; nf++)
#pragma unroll
            for (int mf = 0; mf < 4; mf++) mma16(acc[mf][nf], ah[mf], bl[nf]);
        __syncthreads();
    }
#undef G_LDGX
#undef G_STSX
#undef G_CPAW

#pragma unroll
    for (int mf = 0; mf < 4; mf++) {
#pragma unroll
        for (int h2 = 0; h2 < 2; h2++) {
            const int i = i0 + wi * 64 + mf * 16 + g + h2 * 8;
            const size_t rb = (size_t)i * HQ;
#pragma unroll
            for (int nf = 0; nf < 4; nf++) {
                const int j = wj * 32 + nf * 8 + 2 * tq;
                const float2 bb1 = *reinterpret_cast<const float2*>(b1 + j);
                const float2 bb2 = *reinterpret_cast<const float2*>(b2 + j);
                float v0 = acc[mf][nf][h2 * 2 + 0] + bb1.x + bb2.x;
                float v1 = acc[mf][nf][h2 * 2 + 1] + bb1.y + bb2.y;
                const float2 hv = *reinterpret_cast<const float2*>(hp + rb + j);
                const float2 zz = *reinterpret_cast<const float2*>(zp + rb + j);
                float2 o;
                o.x = (1.f - zz.x) * hv.x + zz.x * tanhf(v0);
                o.y = (1.f - zz.y) * hv.y + zz.y * tanhf(v1);
                *reinterpret_cast<float2*>(outp + rb + j) = o;
            }
        }
    }
}

// ---------------------------------------------------------------------------
// Host launcher
// ---------------------------------------------------------------------------
extern "C" void kernel_launch(void* const* d_in, const int* in_sizes, int n_in,
                              void* d_out, int out_size)
{
    const float* A      = (const float*)d_in[0];
    const float* hidden = (const float*)d_in[1];
    const float* b_ah   = (const float*)d_in[2];
    const float* w_z    = (const float*)d_in[3];
    const float* b_wz   = (const float*)d_in[4];
    const float* u_z    = (const float*)d_in[5];
    const float* b_uz   = (const float*)d_in[6];
    const float* w_r    = (const float*)d_in[7];
    const float* b_wr   = (const float*)d_in[8];
    const float* u_r    = (const float*)d_in[9];
    const float* b_ur   = (const float*)d_in[10];
    const float* w      = (const float*)d_in[11];
    const float* b_w    = (const float*)d_in[12];
    const float* u      = (const float*)d_in[13];
    const float* b_u    = (const float*)d_in[14];
    float* out = (float*)d_out;

    float *ga, *gz, *grh, *h0, *h1;
    uint32_t* Wsp;
    cudaGetSymbolAddress((void**)&ga,  g_a);
    cudaGetSymbolAddress((void**)&gz,  g_z);
    cudaGetSymbolAddress((void**)&grh, g_rh);
    cudaGetSymbolAddress((void**)&h0,  g_h0);
    cudaGetSymbolAddress((void**)&h1,  g_h1);
    cudaGetSymbolAddress((void**)&Wsp, g_Wh);

    cudaFuncSetAttribute(k_mma_a, cudaFuncAttributeMaxDynamicSharedMemorySize, 34816);
    cudaFuncSetAttribute(k_zr,    cudaFuncAttributeMaxDynamicSharedMemorySize, 61440);
    cudaFuncSetAttribute(k_cgate, cudaFuncAttributeMaxDynamicSharedMemorySize, 49152);

    // one fused weight-split launch: grid.y = matrix index 0..5
    k_splith6<<<dim3(16, 6), 256>>>(w_z, u_z, w_r, u_r, w, u, Wsp);

    const float* hpr[4] = { hidden, h0, h1, h0 };
    float*       hnr[4] = { h0, h1, h0, out };

    for (int s = 0; s < 4; s++) {
        const float* hp = hpr[s];
        k_mma_a<<<dim3(4, BQ), 256, 34816>>>(A, hp, b_ah, ga);
        k_zr<<<M2 / 64, 256, 61440>>>(ga, hp, Wsp, b_wz, b_uz, b_wr, b_ur, gz, grh);
        k_cgate<<<M2 / 128, 256, 49152>>>(ga, grh, Wsp, b_w, b_u, hp, gz, hnr[s]);
    }
}